// round 1
// baseline (speedup 1.0000x reference)
#include <cuda_runtime.h>

// Problem: x [32, 512, 512] f32 -> pad 128 each side -> [32, 768, 768]
// -> nearest-neighbor upsample x4 both dims -> out [32, 3072, 3072] f32.
//
// out[b, i, j] = x[b, i/4 - 128, j/4 - 128] if in-bounds else 0.
//
// Since SCALE=4, each aligned float4 of the output row maps to exactly one
// source element: one thread -> one LDG.32 (L2-resident, input is 32MB) and
// one coalesced STG.128. Total DRAM traffic = 1.21 GB stores (minimum).

#define B       32
#define HW      512
#define OW      3072          // (512 + 2*128) * 4
#define OW4     768           // OW / 4  (float4 groups per row)
#define PER_B   (OW * OW4)    // float4s per batch image = 2359296
#define TOTAL   (B * PER_B)   // 75497472 float4s

__global__ __launch_bounds__(256) void scale_layer_kernel(
    const float* __restrict__ x, float4* __restrict__ out)
{
    unsigned idx = blockIdx.x * 256u + threadIdx.x;

    unsigned b    = idx / (unsigned)PER_B;
    unsigned rem  = idx - b * (unsigned)PER_B;
    unsigned orow = rem / (unsigned)OW4;
    unsigned oq   = rem - orow * (unsigned)OW4;

    int r = (int)(orow >> 2) - 128;   // source row
    int c = (int)oq - 128;            // source col (float4 group == source col)

    float v = 0.0f;
    if ((unsigned)r < (unsigned)HW && (unsigned)c < (unsigned)HW) {
        v = x[(size_t)b * (HW * HW) + (unsigned)r * HW + (unsigned)c];
    }
    out[(size_t)idx] = make_float4(v, v, v, v);
}

extern "C" void kernel_launch(void* const* d_in, const int* in_sizes, int n_in,
                              void* d_out, int out_size)
{
    const float* x = (const float*)d_in[0];
    float4* out = (float4*)d_out;
    // TOTAL float4s, 256 threads/block -> 294912 blocks exactly
    scale_layer_kernel<<<TOTAL / 256, 256>>>(x, out);
}

// round 2
// speedup vs baseline: 1.1229x; 1.1229x over previous
#include <cuda_runtime.h>

// x [32, 512, 512] f32 -> pad 128 -> [32,768,768] -> NN upsample x4 -> [32,3072,3072] f32.
// out[b, i, j] = x[b, i/4 - 128, j/4 - 128] if in-bounds else 0.
//
// One thread = 4-output-row x 1-float4 tile (the 4 rows share one source row
// AND one source col, since SCALE=4 in both dims):
//   1 LDG.32 (L2-resident; input = 32MB << 126MB L2)
//   4 STG.128 evict-first, rows 12KB apart, each 512B-contiguous per warp.
// DRAM traffic = 1.21 GB stores (minimum).

#define B       32
#define HW      512
#define OW      3072          // (512 + 2*128) * 4
#define OW4     768           // float4 groups per output row
#define SRCROWS 768           // padded source rows (= output rows / 4)
#define TILES_PER_B (SRCROWS * OW4)       // 589824 tiles per batch image
#define NTILES  (B * TILES_PER_B)         // 18874368 total tiles

__global__ __launch_bounds__(256) void scale_layer_kernel(
    const float* __restrict__ x, float4* __restrict__ out)
{
    unsigned idx = blockIdx.x * 256u + threadIdx.x;

    unsigned b     = idx / (unsigned)TILES_PER_B;
    unsigned rem   = idx - b * (unsigned)TILES_PER_B;
    unsigned orow4 = rem / (unsigned)OW4;     // padded source row [0,768)
    unsigned oq    = rem - orow4 * (unsigned)OW4;  // float4 col group [0,768)

    int r = (int)orow4 - 128;                 // source row
    int c = (int)oq - 128;                    // source col

    float v = 0.0f;
    if ((unsigned)r < (unsigned)HW && (unsigned)c < (unsigned)HW) {
        v = __ldg(&x[(size_t)b * (HW * HW) + (unsigned)r * HW + (unsigned)c]);
    }
    float4 v4 = make_float4(v, v, v, v);

    // Output base: row orow4*4 of batch b, float4 column oq.
    float4* p = out + ((size_t)b * OW + (size_t)orow4 * 4u) * OW4 + oq;
    __stcs(p,           v4);
    __stcs(p + OW4,     v4);
    __stcs(p + 2 * OW4, v4);
    __stcs(p + 3 * OW4, v4);
}

extern "C" void kernel_launch(void* const* d_in, const int* in_sizes, int n_in,
                              void* d_out, int out_size)
{
    const float* x = (const float*)d_in[0];
    float4* out = (float4*)d_out;
    // NTILES / 256 = 73728 blocks exactly
    scale_layer_kernel<<<NTILES / 256, 256>>>(x, out);
}